// round 15
// baseline (speedup 1.0000x reference)
#include <cuda_runtime.h>

#define NATOMS  1024
#define NBATCH  32
#define TPB     128
#define JQ      4              // j-quarters
#define JTILE   256            // atoms per j-quarter
#define NQUADS  64             // quads per j-quarter
// grid = 32 batches * 4 i-chunks * 4 j-quarters = 512 blocks of 128 threads
// each thread owns i-atoms (chunk*256 + tid) and (chunk*256 + tid + 128)

typedef unsigned long long ull;

__device__ __forceinline__ ull f2pack(float lo, float hi) {
    ull r;
    asm("mov.b64 %0, {%1, %2};" : "=l"(r)
        : "r"(__float_as_uint(lo)), "r"(__float_as_uint(hi)));
    return r;
}
__device__ __forceinline__ void f2unpack(ull v, float& lo, float& hi) {
    unsigned a, b;
    asm("mov.b64 {%0, %1}, %2;" : "=r"(a), "=r"(b) : "l"(v));
    lo = __uint_as_float(a);
    hi = __uint_as_float(b);
}
__device__ __forceinline__ ull f2add(ull a, ull b) {
    ull r; asm("add.rn.f32x2 %0, %1, %2;" : "=l"(r) : "l"(a), "l"(b)); return r;
}
__device__ __forceinline__ ull f2mul(ull a, ull b) {
    ull r; asm("mul.rn.f32x2 %0, %1, %2;" : "=l"(r) : "l"(a), "l"(b)); return r;
}
__device__ __forceinline__ ull f2fma(ull a, ull b, ull c) {
    ull r; asm("fma.rn.f32x2 %0, %1, %2, %3;" : "=l"(r) : "l"(a), "l"(b), "l"(c)); return r;
}

// Pre-pass: 4 blocks per batch; mean + oscillator init (quarter-0 writes out[b]).
__global__ __launch_bounds__(256) void lj_pre(const float* __restrict__ pos,
                                              float* __restrict__ out) {
    __shared__ float wr[8 * 3];
    __shared__ float er[8];
    __shared__ float smean[3];

    const int blk = blockIdx.x;
    const int b   = blk >> 2;
    const int q   = blk & 3;
    const int tid = threadIdx.x;
    const int lane = tid & 31, warp = tid >> 5;
    const float* __restrict__ p = pos + (size_t)b * NATOMS * 3;

    float ax[4], ay[4], az[4];
    float mx = 0.0f, my = 0.0f, mz = 0.0f;
    #pragma unroll
    for (int k = 0; k < 4; k++) {
        const int a = tid + 256 * k;
        ax[k] = p[3 * a + 0]; ay[k] = p[3 * a + 1]; az[k] = p[3 * a + 2];
        mx += ax[k]; my += ay[k]; mz += az[k];
    }
    #pragma unroll
    for (int o = 16; o > 0; o >>= 1) {
        mx += __shfl_xor_sync(0xFFFFFFFFu, mx, o);
        my += __shfl_xor_sync(0xFFFFFFFFu, my, o);
        mz += __shfl_xor_sync(0xFFFFFFFFu, mz, o);
    }
    if (lane == 0) { wr[warp * 3] = mx; wr[warp * 3 + 1] = my; wr[warp * 3 + 2] = mz; }
    __syncthreads();
    if (tid == 0) {
        float sx = 0.0f, sy = 0.0f, sz = 0.0f;
        #pragma unroll
        for (int k = 0; k < 8; k++) { sx += wr[k*3]; sy += wr[k*3+1]; sz += wr[k*3+2]; }
        const float inv_n = 1.0f / (float)NATOMS;
        smean[0] = sx * inv_n; smean[1] = sy * inv_n; smean[2] = sz * inv_n;
    }
    __syncthreads();
    const float cmx = smean[0], cmy = smean[1], cmz = smean[2];

    float e = 0.0f;
    float* __restrict__ f = out + NBATCH + (size_t)b * NATOMS * 3;
    #pragma unroll
    for (int k = 0; k < 4; k++) {
        float xc = ax[k] - cmx, yc = ay[k] - cmy, zc = az[k] - cmz;
        e += fmaf(xc, xc, fmaf(yc, yc, zc * zc));
        if (k == q) {
            const int a = tid + 256 * k;
            f[3 * a + 0] = -0.25f * xc;
            f[3 * a + 1] = -0.25f * yc;
            f[3 * a + 2] = -0.25f * zc;
        }
    }
    e *= 0.125f;
    #pragma unroll
    for (int o = 16; o > 0; o >>= 1) e += __shfl_xor_sync(0xFFFFFFFFu, e, o);
    if (lane == 0) er[warp] = e;
    __syncthreads();
    if (q == 0 && tid == 0) {
        float es = 0.0f;
        #pragma unroll
        for (int k = 0; k < 8; k++) es += er[k];
        out[b] = es;
    }
}

// Minimal LJ core: a = 1/r^2; u = a^3 - 1; ae += u^2 (= e_term + 1, count fixed
// in epilogue); force coef c = a^4 * u = (r^-12 - r^-6)/r^2.
__device__ __forceinline__ void lj_core(
    ull xi2, ull yi2, ull zi2, ull nx2, ull ny2, ull nz2,
    int m, int m0, int m1, bool self_mask, ull MINUS1,
    ull& fx2, ull& fy2, ull& fz2, ull& ae)
{
    ull dx2 = f2add(xi2, nx2);
    ull dy2 = f2add(yi2, ny2);
    ull dz2 = f2add(zi2, nz2);
    ull sq2 = f2mul(dx2, dx2);
    sq2 = f2fma(dy2, dy2, sq2);
    sq2 = f2fma(dz2, dz2, sq2);
    float s0, s1;
    f2unpack(sq2, s0, s1);
    if (self_mask) {                    // self-pair -> rcp underflows to 0
        s0 = (m == m0) ? 3.0e38f : s0;
        s1 = (m == m1) ? 3.0e38f : s1;
    }
    float r0 = __fdividef(1.0f, s0);    // MUFU.RCP (self: -> 0)
    float r1 = __fdividef(1.0f, s1);
    ull a  = f2pack(r0, r1);
    ull a2 = f2mul(a, a);
    ull a3 = f2mul(a2, a);
    ull a4 = f2mul(a2, a2);
    ull um = f2add(a3, MINUS1);         // r^-6 - 1  (self: -1)
    ae = f2fma(um, um, ae);             // += (r^-6 - 1)^2 = e_term + 1 (self: +1)
    ull c2 = f2mul(a4, um);             // (r^-12 - r^-6)/r^2 (self: 0)
    fx2 = f2fma(c2, dx2, fx2);
    fy2 = f2fma(c2, dy2, fy2);
    fz2 = f2fma(c2, dz2, fz2);
}

template <bool SELF>
__device__ __forceinline__ void quad_loop2(
    const ulonglong2* __restrict__ SX, const ulonglong2* __restrict__ SY,
    const ulonglong2* __restrict__ SZ,
    ull xa2, ull ya2, ull za2, ull xb2, ull yb2, ull zb2,
    int qa, int qb, int sub, int slot, ull MINUS1,
    ull& fxa, ull& fya, ull& fza, ull& aea,
    ull& fxb, ull& fyb, ull& fzb, ull& aeb)
{
    // core sub=0 handles quad elems 0,1; sub=1 elems 2,3
    const int a00 = (SELF && sub == 0 && slot == 0) ? qa : -1;
    const int a01 = (SELF && sub == 0 && slot == 1) ? qa : -1;
    const int a10 = (SELF && sub == 1 && slot == 0) ? qa : -1;
    const int a11 = (SELF && sub == 1 && slot == 1) ? qa : -1;
    const int b00 = (SELF && sub == 0 && slot == 0) ? qb : -1;
    const int b01 = (SELF && sub == 0 && slot == 1) ? qb : -1;
    const int b10 = (SELF && sub == 1 && slot == 0) ? qb : -1;
    const int b11 = (SELF && sub == 1 && slot == 1) ? qb : -1;
    #pragma unroll 2
    for (int t = 0; t < NQUADS; t++) {
        ulonglong2 X = SX[t], Y = SY[t], Z = SZ[t];   // broadcast LDS.128 x3
        lj_core(xa2, ya2, za2, X.x, Y.x, Z.x, t, a00, a01, SELF, MINUS1,
                fxa, fya, fza, aea);
        lj_core(xa2, ya2, za2, X.y, Y.y, Z.y, t, a10, a11, SELF, MINUS1,
                fxa, fya, fza, aea);
        lj_core(xb2, yb2, zb2, X.x, Y.x, Z.x, t, b00, b01, SELF, MINUS1,
                fxb, fyb, fzb, aeb);
        lj_core(xb2, yb2, zb2, X.y, Y.y, Z.y, t, b10, b11, SELF, MINUS1,
                fxb, fyb, fzb, aeb);
    }
}

__global__ __launch_bounds__(TPB, 6) void lj_kernel(const float* __restrict__ pos,
                                                    float* __restrict__ out) {
    __shared__ ulonglong2 sxq[NQUADS];   // {x01, x23} negated
    __shared__ ulonglong2 syq[NQUADS];
    __shared__ ulonglong2 szq[NQUADS];
    __shared__ float      ered[4];

    const int bi    = blockIdx.x;
    const int b     = bi >> 4;
    const int chunk = (bi >> 2) & 3;     // i-chunk (256 atoms)
    const int jp    = bi & 3;            // j-quarter (256 atoms)
    const int tid   = threadIdx.x;
    const int lane  = tid & 31;
    const int warp  = tid >> 5;

    const float* __restrict__ p = pos + (size_t)b * NATOMS * 3;

    // stage j-quarter as 64 quads (threads 0..63; 3 aligned float4 loads each)
    if (tid < NQUADS) {
        const float4* pj = (const float4*)(p + 3 * (jp * JTILE + 4 * tid));
        float4 A = pj[0];                // x0 y0 z0 x1
        float4 B = pj[1];                // y1 z1 x2 y2
        float4 C = pj[2];                // z2 x3 y3 z3
        ulonglong2 X, Y, Z;
        X.x = f2pack(-A.x, -A.w); X.y = f2pack(-B.z, -C.y);
        Y.x = f2pack(-A.y, -B.x); Y.y = f2pack(-B.w, -C.z);
        Z.x = f2pack(-A.z, -B.y); Z.y = f2pack(-C.x, -C.w);
        sxq[tid] = X; syq[tid] = Y; szq[tid] = Z;
    }

    // two owned i-atoms
    const int i0 = chunk * JTILE + tid;
    const int i1 = i0 + TPB;
    const float xa = p[3 * i0 + 0], ya = p[3 * i0 + 1], za = p[3 * i0 + 2];
    const float xb = p[3 * i1 + 0], yb = p[3 * i1 + 1], zb = p[3 * i1 + 2];
    __syncthreads();

    const ull xa2 = f2pack(xa, xa), ya2 = f2pack(ya, ya), za2 = f2pack(za, za);
    const ull xb2 = f2pack(xb, xb), yb2 = f2pack(yb, yb), zb2 = f2pack(zb, zb);
    const ull MINUS1 = f2pack(-1.0f, -1.0f);

    ull fxa = 0, fya = 0, fza = 0, aea = 0;
    ull fxb = 0, fyb = 0, fzb = 0, aeb = 0;

    if (chunk == jp) {
        // in-tile indices: atom A = tid, atom B = tid + 128
        const int qa   = tid >> 2;           // A's quad
        const int qb   = 32 + (tid >> 2);    // B's quad
        const int sub  = (tid >> 1) & 1;
        const int slot = tid & 1;
        quad_loop2<true>(sxq, syq, szq, xa2, ya2, za2, xb2, yb2, zb2,
                         qa, qb, sub, slot, MINUS1,
                         fxa, fya, fza, aea, fxb, fyb, fzb, aeb);
    } else {
        quad_loop2<false>(sxq, syq, szq, xa2, ya2, za2, xb2, yb2, zb2,
                          0, 0, 0, 0, MINUS1,
                          fxa, fya, fza, aea, fxb, fyb, fzb, aeb);
    }

    // energy: per i-atom, Sum u^2 over 256 j = Sum(e_term) + 256
    float l0, h0, l1, h1;
    f2unpack(aea, l0, h0);
    f2unpack(aeb, l1, h1);
    float e = 0.5f * ((l0 + h0 + l1 + h1) - 512.0f);

    // forces: out preloaded with oscillator force by lj_pre; 4 partials per atom
    {
        float lo, hi;
        float* __restrict__ fA = out + NBATCH + (size_t)(b * NATOMS + i0) * 3;
        f2unpack(fxa, lo, hi); atomicAdd(fA + 0, 12.0f * (lo + hi));
        f2unpack(fya, lo, hi); atomicAdd(fA + 1, 12.0f * (lo + hi));
        f2unpack(fza, lo, hi); atomicAdd(fA + 2, 12.0f * (lo + hi));
        float* __restrict__ fB = out + NBATCH + (size_t)(b * NATOMS + i1) * 3;
        f2unpack(fxb, lo, hi); atomicAdd(fB + 0, 12.0f * (lo + hi));
        f2unpack(fyb, lo, hi); atomicAdd(fB + 1, 12.0f * (lo + hi));
        f2unpack(fzb, lo, hi); atomicAdd(fB + 2, 12.0f * (lo + hi));
    }

    // energy: warp shuffles -> shared -> one atomicAdd per block
    #pragma unroll
    for (int o = 16; o > 0; o >>= 1)
        e += __shfl_xor_sync(0xFFFFFFFFu, e, o);
    if (lane == 0) ered[warp] = e;
    __syncthreads();
    if (tid == 0) {
        atomicAdd(out + b, ered[0] + ered[1] + ered[2] + ered[3]);
    }
}

extern "C" void kernel_launch(void* const* d_in, const int* in_sizes, int n_in,
                              void* d_out, int out_size) {
    const float* pos = (const float*)d_in[0];
    float* out = (float*)d_out;
    lj_pre<<<4 * NBATCH, 256>>>(pos, out);
    lj_kernel<<<NBATCH * 4 * JQ, TPB>>>(pos, out);
}

// round 16
// speedup vs baseline: 1.2770x; 1.2770x over previous
#include <cuda_runtime.h>

#define NATOMS  1024
#define NBATCH  32
#define NTILE   8
#define TILE    128
#define QUADS   32            // quads of 4 j-atoms per tile
#define NPB     36            // tile-pairs per batch: 8 diag + 28 off-diag
#define THREADS 64            // each thread owns TWO i-atoms (tid, tid+64)
// grid = NBATCH * NPB = 1152 blocks of 64 threads

typedef unsigned long long ull;

__device__ __forceinline__ ull f2pack(float lo, float hi) {
    ull r;
    asm("mov.b64 %0, {%1, %2};" : "=l"(r)
        : "r"(__float_as_uint(lo)), "r"(__float_as_uint(hi)));
    return r;
}
__device__ __forceinline__ void f2unpack(ull v, float& lo, float& hi) {
    unsigned a, b;
    asm("mov.b64 {%0, %1}, %2;" : "=r"(a), "=r"(b) : "l"(v));
    lo = __uint_as_float(a);
    hi = __uint_as_float(b);
}
__device__ __forceinline__ ull f2add(ull a, ull b) {
    ull r; asm("add.rn.f32x2 %0, %1, %2;" : "=l"(r) : "l"(a), "l"(b)); return r;
}
__device__ __forceinline__ ull f2mul(ull a, ull b) {
    ull r; asm("mul.rn.f32x2 %0, %1, %2;" : "=l"(r) : "l"(a), "l"(b)); return r;
}
__device__ __forceinline__ ull f2fma(ull a, ull b, ull c) {
    ull r; asm("fma.rn.f32x2 %0, %1, %2, %3;" : "=l"(r) : "l"(a), "l"(b), "l"(c)); return r;
}

__global__ void lj_zero_out(float* __restrict__ out, int n) {
    int idx = blockIdx.x * blockDim.x + threadIdx.x;
    for (; idx < n; idx += gridDim.x * blockDim.x) out[idx] = 0.0f;
}

// Minimal LJ core: a = 1/r^2; u = a^3 - 1; ae += u^2 (= e_term + 1, count fixed
// in epilogue; self-pair contributes exactly +1); force coef c = a^4*u (self: 0).
__device__ __forceinline__ ull lj_core(
    ull xi2, ull yi2, ull zi2, ull nx2, ull ny2, ull nz2,
    int m, int m0, int m1, bool self_mask, ull MINUS1,
    ull& dx2o, ull& dy2o, ull& dz2o,
    ull& fx2, ull& fy2, ull& fz2, ull& ae)
{
    ull dx2 = f2add(xi2, nx2);
    ull dy2 = f2add(yi2, ny2);
    ull dz2 = f2add(zi2, nz2);
    ull sq2 = f2mul(dx2, dx2);
    sq2 = f2fma(dy2, dy2, sq2);
    sq2 = f2fma(dz2, dz2, sq2);
    float s0, s1;
    f2unpack(sq2, s0, s1);
    if (self_mask) {                    // self-pair -> rcp underflows to 0
        s0 = (m == m0) ? 3.0e38f : s0;
        s1 = (m == m1) ? 3.0e38f : s1;
    }
    float r0 = __fdividef(1.0f, s0);    // MUFU.RCP
    float r1 = __fdividef(1.0f, s1);
    ull a  = f2pack(r0, r1);
    ull a2 = f2mul(a, a);
    ull a3 = f2mul(a2, a);
    ull a4 = f2mul(a2, a2);
    ull um = f2add(a3, MINUS1);         // r^-6 - 1   (self: -1)
    ae = f2fma(um, um, ae);             // += e_term + 1  (self: +1)
    ull c2 = f2mul(a4, um);             // (r^-12 - r^-6)/r^2  (self: 0)
    fx2 = f2fma(c2, dx2, fx2);
    fy2 = f2fma(c2, dy2, fy2);
    fz2 = f2fma(c2, dz2, fz2);
    dx2o = dx2; dy2o = dy2; dz2o = dz2;
    return c2;
}

__global__ __launch_bounds__(THREADS, 10) void lj_kernel(const float* __restrict__ pos,
                                                         float* __restrict__ out) {
    // j-tile in quads: quad q holds atoms 4q..4q+3 (negated)
    __shared__ ulonglong2 sxq[QUADS];      // {x01, x23}
    __shared__ ulonglong2 syq[QUADS];      // {y01, y23}
    __shared__ ulonglong2 szq[QUADS];      // {z01, z23}
    __shared__ ulonglong2 gx[2][QUADS];    // per-warp j-force accumulators
    __shared__ ulonglong2 gy[2][QUADS];
    __shared__ ulonglong2 gz[2][QUADS];
    __shared__ float      wred[2 * 3];
    __shared__ float      ered[2];
    __shared__ float      smean[3];

    const int bi  = blockIdx.x;
    const int b   = bi / NPB;
    int rem = bi - b * NPB;                // tile-pair rank 0..35
    int ta = 0;
    while (rem >= NTILE - ta) { rem -= NTILE - ta; ta++; }
    const int tb = ta + rem;               // ta <= tb
    const bool diag = (ta == tb);

    const int tid  = threadIdx.x;
    const int lane = tid & 31;
    const int warp = tid >> 5;

    const float* __restrict__ p = pos + (size_t)b * NATOMS * 3;

    // two owned i-atoms
    const int i0 = ta * TILE + tid;
    const int i1 = i0 + THREADS;
    const float xa = p[3 * i0 + 0], ya = p[3 * i0 + 1], za = p[3 * i0 + 2];
    const float xb = p[3 * i1 + 0], yb = p[3 * i1 + 1], zb = p[3 * i1 + 2];

    // stage quads (threads 0..31)
    if (tid < QUADS) {
        const int j0 = tb * TILE + 4 * tid;
        float v0x = p[3*j0+0], v0y = p[3*j0+1],  v0z = p[3*j0+2];
        float v1x = p[3*j0+3], v1y = p[3*j0+4],  v1z = p[3*j0+5];
        float v2x = p[3*j0+6], v2y = p[3*j0+7],  v2z = p[3*j0+8];
        float v3x = p[3*j0+9], v3y = p[3*j0+10], v3z = p[3*j0+11];
        ulonglong2 X, Y, Z;
        X.x = f2pack(-v0x, -v1x); X.y = f2pack(-v2x, -v3x);
        Y.x = f2pack(-v0y, -v1y); Y.y = f2pack(-v2y, -v3y);
        Z.x = f2pack(-v0z, -v1z); Z.y = f2pack(-v2z, -v3z);
        sxq[tid] = X; syq[tid] = Y; szq[tid] = Z;
    }
    // zero accumulators
    #pragma unroll
    for (int k = 0; k < 2; k++) {
        ((ull*)gx)[k * 64 + tid] = 0;
        ((ull*)gy)[k * 64 + tid] = 0;
        ((ull*)gz)[k * 64 + tid] = 0;
    }

    // diag blocks compute batch mean (for oscillator); off-diag skip
    if (diag) {
        float mx = 0.0f, my = 0.0f, mz = 0.0f;
        for (int a = tid; a < NATOMS; a += THREADS) {
            mx += p[3 * a + 0];
            my += p[3 * a + 1];
            mz += p[3 * a + 2];
        }
        #pragma unroll
        for (int o = 16; o > 0; o >>= 1) {
            mx += __shfl_xor_sync(0xFFFFFFFFu, mx, o);
            my += __shfl_xor_sync(0xFFFFFFFFu, my, o);
            mz += __shfl_xor_sync(0xFFFFFFFFu, mz, o);
        }
        if (lane == 0) {
            wred[warp * 3 + 0] = mx;
            wred[warp * 3 + 1] = my;
            wred[warp * 3 + 2] = mz;
        }
    }
    __syncthreads();
    if (diag && tid == 0) {
        const float inv_n = 1.0f / (float)NATOMS;
        smean[0] = (wred[0] + wred[3]) * inv_n;
        smean[1] = (wred[1] + wred[4]) * inv_n;
        smean[2] = (wred[2] + wred[5]) * inv_n;
    }
    if (diag) __syncthreads();

    const ull xa2 = f2pack(xa, xa), ya2 = f2pack(ya, ya), za2 = f2pack(za, za);
    const ull xb2 = f2pack(xb, xb), yb2 = f2pack(yb, yb), zb2 = f2pack(zb, zb);
    const ull MINUS1 = f2pack(-1.0f, -1.0f);

    ull fxa = 0, fya = 0, fza = 0, aea = 0;
    ull fxb = 0, fyb = 0, fzb = 0, aeb = 0;

    if (diag) {
        // self-tile: atom a = tid = 4*qa + 2*sub + slot; atom b = tid + 64.
        const int qa   = tid >> 2;
        const int qb   = 16 + qa;
        const int sub  = (tid >> 1) & 1;
        const int slot = tid & 1;
        const int a00 = (sub == 0 && slot == 0) ? qa : -1;
        const int a01 = (sub == 0 && slot == 1) ? qa : -1;
        const int a10 = (sub == 1 && slot == 0) ? qa : -1;
        const int a11 = (sub == 1 && slot == 1) ? qa : -1;
        const int b00 = (sub == 0 && slot == 0) ? qb : -1;
        const int b01 = (sub == 0 && slot == 1) ? qb : -1;
        const int b10 = (sub == 1 && slot == 0) ? qb : -1;
        const int b11 = (sub == 1 && slot == 1) ? qb : -1;
        ull d0, d1, d2;
        #pragma unroll 2
        for (int t = 0; t < QUADS; t++) {
            ulonglong2 X = sxq[t], Y = syq[t], Z = szq[t];
            lj_core(xa2, ya2, za2, X.x, Y.x, Z.x, t, a00, a01, true, MINUS1,
                    d0, d1, d2, fxa, fya, fza, aea);
            lj_core(xa2, ya2, za2, X.y, Y.y, Z.y, t, a10, a11, true, MINUS1,
                    d0, d1, d2, fxa, fya, fza, aea);
            lj_core(xb2, yb2, zb2, X.x, Y.x, Z.x, t, b00, b01, true, MINUS1,
                    d0, d1, d2, fxb, fyb, fzb, aeb);
            lj_core(xb2, yb2, zb2, X.y, Y.y, Z.y, t, b10, b11, true, MINUS1,
                    d0, d1, d2, fxb, fyb, fzb, aeb);
        }
    } else {
        // cross-tile: lane rotation over quads; 128-bit j-RMW per component.
        ulonglong2* __restrict__ GX = gx[warp];
        ulonglong2* __restrict__ GY = gy[warp];
        ulonglong2* __restrict__ GZ = gz[warp];
        ull dax0, day0, daz0, dbx0, dby0, dbz0;
        ull dax1, day1, daz1, dbx1, dby1, dbz1;
        #pragma unroll 2
        for (int t = 0; t < QUADS; t++) {
            const int q = (t + lane) & (QUADS - 1);   // lanes on distinct quads
            ulonglong2 X = sxq[q], Y = syq[q], Z = szq[q];
            ull ca0 = lj_core(xa2, ya2, za2, X.x, Y.x, Z.x, 0, -1, -1, false, MINUS1,
                              dax0, day0, daz0, fxa, fya, fza, aea);
            ull cb0 = lj_core(xb2, yb2, zb2, X.x, Y.x, Z.x, 0, -1, -1, false, MINUS1,
                              dbx0, dby0, dbz0, fxb, fyb, fzb, aeb);
            ull ca1 = lj_core(xa2, ya2, za2, X.y, Y.y, Z.y, 0, -1, -1, false, MINUS1,
                              dax1, day1, daz1, fxa, fya, fza, aea);
            ull cb1 = lj_core(xb2, yb2, zb2, X.y, Y.y, Z.y, 0, -1, -1, false, MINUS1,
                              dbx1, dby1, dbz1, fxb, fyb, fzb, aeb);
            ulonglong2 vx = GX[q];
            vx.x = f2fma(cb0, dbx0, f2fma(ca0, dax0, vx.x));
            vx.y = f2fma(cb1, dbx1, f2fma(ca1, dax1, vx.y));
            GX[q] = vx;
            ulonglong2 vy = GY[q];
            vy.x = f2fma(cb0, dby0, f2fma(ca0, day0, vy.x));
            vy.y = f2fma(cb1, dby1, f2fma(ca1, day1, vy.y));
            GY[q] = vy;
            ulonglong2 vz = GZ[q];
            vz.x = f2fma(cb0, dbz0, f2fma(ca0, daz0, vz.x));
            vz.y = f2fma(cb1, dbz1, f2fma(ca1, daz1, vz.y));
            GZ[q] = vz;
        }
    }

    // energy: each core added e_term + 1; 256 core-lane terms per thread total
    const float ew = diag ? 0.5f : 1.0f;
    float e;
    {
        float l0, h0, l1, h1;
        f2unpack(aea, l0, h0);
        f2unpack(aeb, l1, h1);
        e = ew * ((l0 + h0 + l1 + h1) - 256.0f);
    }

    float fax, fay, faz, fbx, fby, fbz;
    {
        float lo, hi;
        f2unpack(fxa, lo, hi); fax = 12.0f * (lo + hi);
        f2unpack(fya, lo, hi); fay = 12.0f * (lo + hi);
        f2unpack(fza, lo, hi); faz = 12.0f * (lo + hi);
        f2unpack(fxb, lo, hi); fbx = 12.0f * (lo + hi);
        f2unpack(fyb, lo, hi); fby = 12.0f * (lo + hi);
        f2unpack(fzb, lo, hi); fbz = 12.0f * (lo + hi);
    }

    if (diag) {
        // oscillator: each i belongs to exactly one diag block
        float xc = xa - smean[0], yc = ya - smean[1], zc = za - smean[2];
        e  += 0.125f * fmaf(xc, xc, fmaf(yc, yc, zc * zc));
        fax -= 0.25f * xc; fay -= 0.25f * yc; faz -= 0.25f * zc;
        xc = xb - smean[0]; yc = yb - smean[1]; zc = zb - smean[2];
        e  += 0.125f * fmaf(xc, xc, fmaf(yc, yc, zc * zc));
        fbx -= 0.25f * xc; fby -= 0.25f * yc; fbz -= 0.25f * zc;
    }

    // i-side forces (output zero-initialized by lj_zero_out)
    float* __restrict__ fA = out + NBATCH + (size_t)(b * NATOMS + i0) * 3;
    atomicAdd(fA + 0, fax);
    atomicAdd(fA + 1, fay);
    atomicAdd(fA + 2, faz);
    float* __restrict__ fB = out + NBATCH + (size_t)(b * NATOMS + i1) * 3;
    atomicAdd(fB + 0, fbx);
    atomicAdd(fB + 1, fby);
    atomicAdd(fB + 2, fbz);

    __syncthreads();

    // j-side forces (off-diag only): reduce 2 warp copies per quad, negate, scale
    if (!diag && tid < QUADS) {
        ulonglong2 v0 = gx[0][tid], v1 = gx[1][tid];
        ull sx01 = f2add(v0.x, v1.x), sx23 = f2add(v0.y, v1.y);
        v0 = gy[0][tid]; v1 = gy[1][tid];
        ull sy01 = f2add(v0.x, v1.x), sy23 = f2add(v0.y, v1.y);
        v0 = gz[0][tid]; v1 = gz[1][tid];
        ull sz01 = f2add(v0.x, v1.x), sz23 = f2add(v0.y, v1.y);
        float x0, x1, x2, x3, y0, y1, y2, y3, z0, z1, z2, z3;
        f2unpack(sx01, x0, x1); f2unpack(sx23, x2, x3);
        f2unpack(sy01, y0, y1); f2unpack(sy23, y2, y3);
        f2unpack(sz01, z0, z1); f2unpack(sz23, z2, z3);
        const int j0 = tb * TILE + 4 * tid;
        float* __restrict__ fj = out + NBATCH + (size_t)(b * NATOMS + j0) * 3;
        atomicAdd(fj + 0,  -12.0f * x0);
        atomicAdd(fj + 1,  -12.0f * y0);
        atomicAdd(fj + 2,  -12.0f * z0);
        atomicAdd(fj + 3,  -12.0f * x1);
        atomicAdd(fj + 4,  -12.0f * y1);
        atomicAdd(fj + 5,  -12.0f * z1);
        atomicAdd(fj + 6,  -12.0f * x2);
        atomicAdd(fj + 7,  -12.0f * y2);
        atomicAdd(fj + 8,  -12.0f * z2);
        atomicAdd(fj + 9,  -12.0f * x3);
        atomicAdd(fj + 10, -12.0f * y3);
        atomicAdd(fj + 11, -12.0f * z3);
    }

    // energy: warp shuffles -> shared -> one atomicAdd per block
    #pragma unroll
    for (int o = 16; o > 0; o >>= 1)
        e += __shfl_xor_sync(0xFFFFFFFFu, e, o);
    if (lane == 0) ered[warp] = e;
    __syncthreads();
    if (tid == 0) atomicAdd(out + b, ered[0] + ered[1]);
}

extern "C" void kernel_launch(void* const* d_in, const int* in_sizes, int n_in,
                              void* d_out, int out_size) {
    const float* pos = (const float*)d_in[0];
    float* out = (float*)d_out;
    lj_zero_out<<<148, 256>>>(out, out_size);
    lj_kernel<<<NBATCH * NPB, THREADS>>>(pos, out);
}